// round 1
// baseline (speedup 1.0000x reference)
#include <cuda_runtime.h>

#define NN 100000
#define NE 1600000

// ---------------- device scratch (allocation-free: __device__ globals) ----------------
__device__ float gP [NN*32];   // Z_nodes @ Wg
__device__ float gQ [NN*32];   // Z_nodes @ Ws
__device__ float gAg[NN*32];   // segsum(tanh_g, src)
__device__ float gAs[NN*32];   // segsum(tanh_s, src)
__device__ float gR [NN*32];   // residual R
__device__ float gRW[NN*32];   // R @ W_emb
__device__ float gY [NN*32];   // Z rows < NN (node view of per-edge Z)
__device__ float gTG[NN*32];   // tanh_g for edges < NN
__device__ float gTS[NN*32];   // tanh_s for edges < NN
__device__ float gWgT[1024];
__device__ float gWsT[1024];
__device__ float gMg[1024];    // Wg^T @ W_emb
__device__ float gMs[1024];    // Ws^T @ W_emb

__device__ __forceinline__ void red4(float* p, float4 v) {
    unsigned long long ga = (unsigned long long)__cvta_generic_to_global((void*)p);
    asm volatile("red.global.add.v4.f32 [%0], {%1,%2,%3,%4};"
                 :: "l"(ga), "f"(v.x), "f"(v.y), "f"(v.z), "f"(v.w) : "memory");
}

__device__ __forceinline__ float4 f4sub(float4 a, float4 b) {
    return make_float4(a.x-b.x, a.y-b.y, a.z-b.z, a.w-b.w);
}

// ---------------- prep: transposes + fused 32x32 weight products ----------------
__global__ void k_prep(const float* __restrict__ Wg, const float* __restrict__ Ws,
                       const float* __restrict__ We) {
    int t = threadIdx.x;          // 0..1023
    int i = t >> 5, j = t & 31;   // output (i,j)
    gWgT[t] = Wg[j*32 + i];
    gWsT[t] = Ws[j*32 + i];
    float mg = 0.f, ms = 0.f;
    #pragma unroll
    for (int k = 0; k < 32; k++) {
        float we = We[k*32 + j];
        mg += Wg[k*32 + i] * we;   // Mg[i][j] = sum_k Wg[k][i] * We[k][j]
        ms += Ws[k*32 + i] * we;
    }
    gMg[t] = mg; gMs[t] = ms;
}

__global__ void k_zero() {
    int idx = blockIdx.x * blockDim.x + threadIdx.x;   // NN*8 float4 slots
    float4 z = make_float4(0.f, 0.f, 0.f, 0.f);
    ((float4*)gAg)[idx] = z;
    ((float4*)gAs)[idx] = z;
}

// ---------------- init: segsum(xE, src) ----------------
__global__ __launch_bounds__(256) void k_edge_init(const float4* __restrict__ xE4,
                                                   const int* __restrict__ src) {
    int idx = blockIdx.x * blockDim.x + threadIdx.x;   // NE*8
    int e = idx >> 3, c = idx & 7;
    int s = __ldg(src + e);
    float4 v = __ldg(xE4 + idx);
    red4(gAg + s*32 + c*4, v);
}

__global__ __launch_bounds__(256) void k_node_init(const float4* __restrict__ D4,
                                                   float4* __restrict__ outR) {
    int idx = blockIdx.x * blockDim.x + threadIdx.x;   // NN*8
    float4 a = ((const float4*)gAg)[idx];
    float4 d = __ldg(D4 + idx);
    float4 r = f4sub(d, a);
    ((float4*)gR)[idx] = r;
    outR[idx] = r;
    ((float4*)gAg)[idx] = make_float4(0.f, 0.f, 0.f, 0.f);
}

// Y[e<NN] = xE[e] + ew[e]*(R[s]-R[d])
__global__ __launch_bounds__(256) void k_y0(const float4* __restrict__ xE4,
                                            const float* __restrict__ ew,
                                            const int* __restrict__ src,
                                            const int* __restrict__ dst) {
    int idx = blockIdx.x * blockDim.x + threadIdx.x;   // NN*8
    int e = idx >> 3, c = idx & 7;
    int s = __ldg(src + e), d = __ldg(dst + e);
    float w = __ldg(ew + e);
    float4 x = __ldg(xE4 + idx);
    float4 rs = ((const float4*)gR)[s*8 + c];
    float4 rd = ((const float4*)gR)[d*8 + c];
    float4 y;
    y.x = x.x + w*(rs.x - rd.x);
    y.y = x.y + w*(rs.y - rd.y);
    y.z = x.z + w*(rs.z - rd.z);
    y.w = x.w + w*(rs.w - rd.w);
    ((float4*)gY)[idx] = y;
}

// ---------------- P = Y@Wg, Q = Y@Ws (node-level tiny GEMM) ----------------
__global__ __launch_bounds__(256) void k_pq(const float* __restrict__ Wg,
                                            const float* __restrict__ Ws) {
    __shared__ float sWg[1024], sWs[1024];
    int t = threadIdx.x;
    for (int i = t; i < 1024; i += 256) { sWg[i] = Wg[i]; sWs[i] = Ws[i]; }
    __syncthreads();
    int idx = blockIdx.x * 256 + t;        // NN*8
    int n = idx >> 3, j0 = (idx & 7) * 4;
    float y[32];
    const float4* Yr = (const float4*)gY + n*8;
    #pragma unroll
    for (int k4 = 0; k4 < 8; k4++) {
        float4 v = Yr[k4];
        y[4*k4+0]=v.x; y[4*k4+1]=v.y; y[4*k4+2]=v.z; y[4*k4+3]=v.w;
    }
    float4 p = make_float4(0,0,0,0), q = make_float4(0,0,0,0);
    #pragma unroll
    for (int k = 0; k < 32; k++) {
        float yk = y[k];
        float4 wg = *(const float4*)(sWg + k*32 + j0);
        float4 ws = *(const float4*)(sWs + k*32 + j0);
        p.x += yk*wg.x; p.y += yk*wg.y; p.z += yk*wg.z; p.w += yk*wg.w;
        q.x += yk*ws.x; q.y += yk*ws.y; q.z += yk*ws.z; q.w += yk*ws.w;
    }
    ((float4*)gP)[idx] = p;
    ((float4*)gQ)[idx] = q;
}

// ---------------- main edge kernel: tanh + segment-sum atomics (NO per-edge GEMM) ----------------
__global__ __launch_bounds__(256) void k_edge(const float* __restrict__ ew,
                                              const int* __restrict__ src,
                                              const int* __restrict__ dst) {
    int idx = blockIdx.x * blockDim.x + threadIdx.x;   // NE*8
    int e = idx >> 3, c = idx & 7;
    int s = __ldg(src + e), d = __ldg(dst + e);
    float w = __ldg(ew + e);
    const float4* P4 = (const float4*)gP;
    const float4* Q4 = (const float4*)gQ;
    float4 ps = __ldg(P4 + s*8 + c);
    float4 pd = __ldg(P4 + d*8 + c);
    float4 qd = __ldg(Q4 + d*8 + c);
    float4 tg, ts;
    tg.x = tanhf(w*(ps.x-pd.x)); tg.y = tanhf(w*(ps.y-pd.y));
    tg.z = tanhf(w*(ps.z-pd.z)); tg.w = tanhf(w*(ps.w-pd.w));
    ts.x = tanhf(w*qd.x); ts.y = tanhf(w*qd.y);
    ts.z = tanhf(w*qd.z); ts.w = tanhf(w*qd.w);
    red4(gAg + s*32 + c*4, tg);
    red4(gAs + s*32 + c*4, ts);
    if (e < NN) {               // only rows < NN feed the next iteration
        ((float4*)gTG)[idx] = tg;
        ((float4*)gTS)[idx] = ts;
    }
}

// ---------------- R = D - (Ag@WgT + As@WsT); reset accumulators ----------------
__global__ __launch_bounds__(256) void k_node_main(const float4* __restrict__ D4,
                                                   float4* __restrict__ outR) {
    __shared__ float sWgT[1024], sWsT[1024];
    int t = threadIdx.x;
    for (int i = t; i < 1024; i += 256) { sWgT[i] = gWgT[i]; sWsT[i] = gWsT[i]; }
    __syncthreads();
    int idx = blockIdx.x * 256 + t;        // NN*8
    int n = idx >> 3, j0 = (idx & 7) * 4;
    float a[32], b[32];
    const float4* Ar = (const float4*)gAg + n*8;
    const float4* Br = (const float4*)gAs + n*8;
    #pragma unroll
    for (int k4 = 0; k4 < 8; k4++) {
        float4 va = Ar[k4], vb = Br[k4];
        a[4*k4+0]=va.x; a[4*k4+1]=va.y; a[4*k4+2]=va.z; a[4*k4+3]=va.w;
        b[4*k4+0]=vb.x; b[4*k4+1]=vb.y; b[4*k4+2]=vb.z; b[4*k4+3]=vb.w;
    }
    float4 acc = make_float4(0,0,0,0);
    #pragma unroll
    for (int k = 0; k < 32; k++) {
        float4 wg = *(const float4*)(sWgT + k*32 + j0);
        float4 ws = *(const float4*)(sWsT + k*32 + j0);
        acc.x += a[k]*wg.x + b[k]*ws.x;
        acc.y += a[k]*wg.y + b[k]*ws.y;
        acc.z += a[k]*wg.z + b[k]*ws.z;
        acc.w += a[k]*wg.w + b[k]*ws.w;
    }
    float4 dd = __ldg(D4 + idx);
    float4 r = f4sub(dd, acc);
    __syncthreads();   // all 8 threads of each row finished reading Ag/As
    float4 z = make_float4(0,0,0,0);
    ((float4*)gAg)[idx] = z;
    ((float4*)gAs)[idx] = z;
    ((float4*)gR)[idx] = r;
    outR[idx] = r;
}

// ---------------- Y = (TG@WgT + TS@WsT) + ew*(R[s]-R[d]), rows < NN ----------------
__global__ __launch_bounds__(256) void k_zpart(const float* __restrict__ ew,
                                               const int* __restrict__ src,
                                               const int* __restrict__ dst) {
    __shared__ float sWgT[1024], sWsT[1024];
    int t = threadIdx.x;
    for (int i = t; i < 1024; i += 256) { sWgT[i] = gWgT[i]; sWsT[i] = gWsT[i]; }
    __syncthreads();
    int idx = blockIdx.x * 256 + t;        // NN*8
    int e = idx >> 3, c = idx & 7, j0 = c * 4;
    float a[32], b[32];
    const float4* Ar = (const float4*)gTG + e*8;
    const float4* Br = (const float4*)gTS + e*8;
    #pragma unroll
    for (int k4 = 0; k4 < 8; k4++) {
        float4 va = Ar[k4], vb = Br[k4];
        a[4*k4+0]=va.x; a[4*k4+1]=va.y; a[4*k4+2]=va.z; a[4*k4+3]=va.w;
        b[4*k4+0]=vb.x; b[4*k4+1]=vb.y; b[4*k4+2]=vb.z; b[4*k4+3]=vb.w;
    }
    float4 acc = make_float4(0,0,0,0);
    #pragma unroll
    for (int k = 0; k < 32; k++) {
        float4 wg = *(const float4*)(sWgT + k*32 + j0);
        float4 ws = *(const float4*)(sWsT + k*32 + j0);
        acc.x += a[k]*wg.x + b[k]*ws.x;
        acc.y += a[k]*wg.y + b[k]*ws.y;
        acc.z += a[k]*wg.z + b[k]*ws.z;
        acc.w += a[k]*wg.w + b[k]*ws.w;
    }
    int s = __ldg(src + e), d = __ldg(dst + e);
    float w = __ldg(ew + e);
    float4 rs = ((const float4*)gR)[s*8 + c];
    float4 rd = ((const float4*)gR)[d*8 + c];
    acc.x += w*(rs.x-rd.x); acc.y += w*(rs.y-rd.y);
    acc.z += w*(rs.z-rd.z); acc.w += w*(rs.w-rd.w);
    ((float4*)gY)[idx] = acc;
}

// ---------------- RW = R @ W_emb ----------------
__global__ __launch_bounds__(256) void k_rw(const float* __restrict__ We) {
    __shared__ float sW[1024];
    int t = threadIdx.x;
    for (int i = t; i < 1024; i += 256) sW[i] = We[i];
    __syncthreads();
    int idx = blockIdx.x * 256 + t;        // NN*8
    int n = idx >> 3, j0 = (idx & 7) * 4;
    float r[32];
    const float4* Rr = (const float4*)gR + n*8;
    #pragma unroll
    for (int k4 = 0; k4 < 8; k4++) {
        float4 v = Rr[k4];
        r[4*k4+0]=v.x; r[4*k4+1]=v.y; r[4*k4+2]=v.z; r[4*k4+3]=v.w;
    }
    float4 acc = make_float4(0,0,0,0);
    #pragma unroll
    for (int k = 0; k < 32; k++) {
        float4 w4 = *(const float4*)(sW + k*32 + j0);
        acc.x += r[k]*w4.x; acc.y += r[k]*w4.y;
        acc.z += r[k]*w4.z; acc.w += r[k]*w4.w;
    }
    ((float4*)gRW)[idx] = acc;
}

// ---------------- final: Xref = TG@Mg + TS@Ms ; X = Xref + ew*(RW[s]-RW[d]) ----------------
__global__ __launch_bounds__(256) void k_out(const float* __restrict__ ew,
                                             const int* __restrict__ src,
                                             const int* __restrict__ dst,
                                             float4* __restrict__ outX,
                                             float4* __restrict__ outXref) {
    __shared__ float sMg[1024], sMs[1024];
    __shared__ float stg[32][33], sts[32][33];
    int t = threadIdx.x;
    for (int i = t; i < 1024; i += 256) { sMg[i] = gMg[i]; sMs[i] = gMs[i]; }
    int idx = blockIdx.x * 256 + t;        // NE*8
    int e = idx >> 3, c = idx & 7, el = t >> 3;
    int s = __ldg(src + e), d = __ldg(dst + e);
    float w = __ldg(ew + e);
    const float4* P4 = (const float4*)gP;
    const float4* Q4 = (const float4*)gQ;
    float4 ps = __ldg(P4 + s*8 + c);
    float4 pd = __ldg(P4 + d*8 + c);
    float4 qd = __ldg(Q4 + d*8 + c);
    int k0 = c * 4;
    stg[el][k0+0] = tanhf(w*(ps.x-pd.x));
    stg[el][k0+1] = tanhf(w*(ps.y-pd.y));
    stg[el][k0+2] = tanhf(w*(ps.z-pd.z));
    stg[el][k0+3] = tanhf(w*(ps.w-pd.w));
    sts[el][k0+0] = tanhf(w*qd.x);
    sts[el][k0+1] = tanhf(w*qd.y);
    sts[el][k0+2] = tanhf(w*qd.z);
    sts[el][k0+3] = tanhf(w*qd.w);
    __syncthreads();
    float4 xr = make_float4(0,0,0,0);
    int j0 = c * 4;
    #pragma unroll
    for (int k = 0; k < 32; k++) {
        float tgk = stg[el][k], tsk = sts[el][k];
        float4 mg = *(const float4*)(sMg + k*32 + j0);
        float4 ms = *(const float4*)(sMs + k*32 + j0);
        xr.x += tgk*mg.x + tsk*ms.x;
        xr.y += tgk*mg.y + tsk*ms.y;
        xr.z += tgk*mg.z + tsk*ms.z;
        xr.w += tgk*mg.w + tsk*ms.w;
    }
    const float4* RW4 = (const float4*)gRW;
    float4 rs = __ldg(RW4 + s*8 + c);
    float4 rd = __ldg(RW4 + d*8 + c);
    float4 x;
    x.x = xr.x + w*(rs.x-rd.x);
    x.y = xr.y + w*(rs.y-rd.y);
    x.z = xr.z + w*(rs.z-rd.z);
    x.w = xr.w + w*(rs.w-rd.w);
    outX[idx] = x;
    outXref[idx] = xr;
}

// ---------------- launch ----------------
extern "C" void kernel_launch(void* const* d_in, const int* in_sizes, int n_in,
                              void* d_out, int out_size) {
    const float* D  = (const float*)d_in[0];
    const float* xE = (const float*)d_in[1];
    const float* ew = (const float*)d_in[2];
    const float* Wg = (const float*)d_in[3];
    const float* Ws = (const float*)d_in[4];
    const float* We = (const float*)d_in[5];
    const int* eidx = (const int*)d_in[6];
    const int* src = eidx;
    const int* dst = eidx + NE;
    float* out = (float*)d_out;
    float4* outX    = (float4*)out;
    float4* outXref = (float4*)(out + (size_t)NE * 32);
    float4* outR    = (float4*)(out + (size_t)2 * NE * 32);

    const int BN = 256;
    const int gN8 = NN * 8 / BN;   // 3125
    const int gE8 = NE * 8 / BN;   // 50000

    k_prep<<<1, 1024>>>(Wg, Ws, We);
    k_zero<<<gN8, BN>>>();
    k_edge_init<<<gE8, BN>>>((const float4*)xE, src);
    k_node_init<<<gN8, BN>>>((const float4*)D, outR);
    k_y0<<<gN8, BN>>>((const float4*)xE, ew, src, dst);
    for (int it = 0; it < 3; ++it) {
        k_pq<<<gN8, BN>>>(Wg, Ws);
        k_edge<<<gE8, BN>>>(ew, src, dst);
        k_node_main<<<gN8, BN>>>((const float4*)D, outR);
        if (it < 2) k_zpart<<<gN8, BN>>>(ew, src, dst);
    }
    k_rw<<<gN8, BN>>>(We);
    k_out<<<gE8, BN>>>(ew, src, dst, outX, outXref);
}